// round 5
// baseline (speedup 1.0000x reference)
#include <cuda_runtime.h>
#include <cuda_fp16.h>

#define NN 50000
#define EE 800000
#define FULL 0xffffffffu
#define SCAN_BLOCKS 49

// ---- scratch (static device memory) ----
__device__ __align__(16) float d_x[NN * 32];
__device__ __align__(16) float d_id[NN * 64];
__device__ __align__(16) __half d_h1h[NN * 256];
__device__ __align__(16) __half d_hmidh[NN * 256];
__device__ __align__(16) __half d_h2h[NN * 64];
__device__ __align__(16) float d_as1[NN * 4];
__device__ __align__(16) float d_ad1[NN * 4];
__device__ __align__(16) float d_wt[64 * 256];
__device__ __align__(16) float d_was1[32 * 4];
__device__ __align__(16) float d_wad1[32 * 4];
__device__ float d_as2[NN];
__device__ float d_ad2[NN];
__device__ float d_pool[64];
__device__ int d_deg[NN];
__device__ int d_off[NN + 1];
__device__ int d_fill[NN];
__device__ int d_csrc[EE];
__device__ int d_bsum[SCAN_BLOCKS];
__device__ int d_boff[SCAN_BLOCKS];
__device__ int d_is64;

__device__ __forceinline__ float wredsum(float v) {
#pragma unroll
    for (int o = 16; o; o >>= 1) v += __shfl_xor_sync(FULL, v, o);
    return v;
}
__device__ __forceinline__ float lrelu(float x) { return x > 0.f ? x : 0.2f * x; }
__device__ __forceinline__ float elu1(float x) { return x > 0.f ? x : expm1f(x); }

// K0: detect edge_index dtype (int64 values < 50000 -> high words all zero).
__global__ void k_detect(const int* __restrict__ w) {
    if (threadIdx.x == 0) {
        int all0 = 1;
#pragma unroll 1
        for (int i = 0; i < 64; i++)
            if (w[2 * i + 1] != 0) { all0 = 0; break; }
        d_is64 = all0;
    }
}

__global__ void k_zero() {
    int i = blockIdx.x * 256 + threadIdx.x;
    if (i < NN) d_deg[i] = 0;
    if (i < 64) d_pool[i] = 0.f;
}

// fold attention vectors into weight space: was1[k][h] = sum_c W[k,h*64+c]*att_src[h,c]
__global__ void k_prep(const float* __restrict__ W, const float* __restrict__ as_,
                       const float* __restrict__ ad_) {
    int t = threadIdx.x;
    if (t < 128) {
        int k = t >> 2, h = t & 3;
        float sa = 0.f, sd = 0.f;
#pragma unroll 8
        for (int c = 0; c < 64; c++) {
            float w = W[k * 256 + h * 64 + c];
            sa = fmaf(w, as_[h * 64 + c], sa);
            sd = fmaf(w, ad_[h * 64 + c], sd);
        }
        d_was1[k * 4 + h] = sa;
        d_wad1[k * 4 + h] = sd;
    }
}

__global__ void k_hist(const int* __restrict__ eiw) {
    int e = blockIdx.x * 256 + threadIdx.x;
    int dst = d_is64 ? eiw[2 * (EE + e)] : eiw[EE + e];
    dst = min(max(dst, 0), NN - 1);
    atomicAdd(&d_deg[dst], 1);
}

// 3-phase scan: per-block scan -> block-sum scan -> add offsets.
__global__ void k_scan1() {
    __shared__ int ws[32];
    int t = threadIdx.x, lane = t & 31, wid = t >> 5;
    int i = blockIdx.x * 1024 + t;
    int v = (i < NN) ? d_deg[i] : 0;
    int x = v;
#pragma unroll
    for (int o = 1; o < 32; o <<= 1) {
        int y = __shfl_up_sync(FULL, x, o);
        if (lane >= o) x += y;
    }
    if (lane == 31) ws[wid] = x;
    __syncthreads();
    if (t < 32) {
        int s = ws[t];
#pragma unroll
        for (int o = 1; o < 32; o <<= 1) {
            int y = __shfl_up_sync(FULL, s, o);
            if (t >= o) s += y;
        }
        ws[t] = s;
    }
    __syncthreads();
    int excl = x - v + (wid > 0 ? ws[wid - 1] : 0);
    if (i < NN) d_off[i] = excl;
    if (t == 1023) d_bsum[blockIdx.x] = excl + v;
}

__global__ void k_scan2() {
    __shared__ int sh[64];
    int t = threadIdx.x;
    int v = (t < SCAN_BLOCKS) ? d_bsum[t] : 0;
    sh[t] = v;
    __syncthreads();
#pragma unroll
    for (int o = 1; o < 64; o <<= 1) {
        int y = (t >= o) ? sh[t - o] : 0;
        __syncthreads();
        sh[t] += y;
        __syncthreads();
    }
    if (t < SCAN_BLOCKS) d_boff[t] = sh[t] - v;
}

__global__ void k_scan3() {
    int i = blockIdx.x * 1024 + threadIdx.x;
    if (i < NN) {
        int o = d_off[i] + d_boff[blockIdx.x];
        d_off[i] = o;
        d_fill[i] = o;
    }
    if (i == 0) d_off[NN] = EE;
}

__global__ void k_scatter(const int* __restrict__ eiw) {
    int e = blockIdx.x * 256 + threadIdx.x;
    int src, dst;
    if (d_is64) { src = eiw[2 * e]; dst = eiw[2 * (EE + e)]; }
    else        { src = eiw[e];     dst = eiw[EE + e]; }
    src = min(max(src, 0), NN - 1);
    dst = min(max(dst, 0), NN - 1);
    int pos = atomicAdd(&d_fill[dst], 1);
    d_csrc[pos] = src;
}

// K1: node encoder Linear(4,32)+relu+LN(32), plus gat1 attention scalars
// via folded vectors (a_s = x @ was1). 8 nodes/block, 1 warp/node.
__global__ void k_encode(const float* __restrict__ pos, const float* __restrict__ deg,
                         const float* __restrict__ W, const float* __restrict__ b,
                         const float* __restrict__ g, const float* __restrict__ be) {
    int node = blockIdx.x * 8 + (threadIdx.x >> 5);
    int c = threadIdx.x & 31;
    float p0 = pos[node * 3], p1 = pos[node * 3 + 1], p2 = pos[node * 3 + 2], dgr = deg[node];
    float v = fmaf(p0, W[c], fmaf(p1, W[32 + c], fmaf(p2, W[64 + c], fmaf(dgr, W[96 + c], b[c]))));
    v = fmaxf(v, 0.f);
    float m = wredsum(v) * (1.f / 32.f);
    float d = v - m;
    float var = wredsum(d * d) * (1.f / 32.f);
    float xv = d * rsqrtf(var + 1e-5f) * g[c] + be[c];
    d_x[node * 32 + c] = xv;
    float4 wa = ((const float4*)d_was1)[c];
    float4 wd = ((const float4*)d_wad1)[c];
    float s0 = wredsum(xv * wa.x);
    float s1 = wredsum(xv * wa.y);
    float s2 = wredsum(xv * wa.z);
    float s3 = wredsum(xv * wa.w);
    float t0 = wredsum(xv * wd.x);
    float t1 = wredsum(xv * wd.y);
    float t2 = wredsum(xv * wd.z);
    float t3 = wredsum(xv * wd.w);
    if (c < 4) {
        d_as1[node * 4 + c] = c == 0 ? s0 : c == 1 ? s1 : c == 2 ? s2 : s3;
        d_ad1[node * 4 + c] = c == 0 ? t0 : c == 1 ? t1 : c == 2 ? t2 : t3;
    }
}

// K2: gat1 linear h1 = x@W (fp16 out) + fused identity projection. 16 nodes/block.
__global__ void k_gat1_lin(const float* __restrict__ W, const float* __restrict__ pw,
                           const float* __restrict__ pb) {
    __shared__ float xs[16][32];
    int t = threadIdx.x;
    int n0 = blockIdx.x * 16;
    for (int i = t; i < 512; i += 256) xs[i >> 5][i & 31] = d_x[n0 * 32 + i];
    float wreg[32];
#pragma unroll
    for (int k = 0; k < 32; k++) wreg[k] = W[k * 256 + t];
    __syncthreads();
#pragma unroll 1
    for (int nn = 0; nn < 16; nn++) {
        float hv = 0.f;
#pragma unroll
        for (int k = 0; k < 32; k++) hv = fmaf(xs[nn][k], wreg[k], hv);
        d_h1h[(n0 + nn) * 256 + t] = __float2half_rn(hv);
    }
    int c = t & 63, gbase = t >> 6;
    float preg[32];
#pragma unroll
    for (int k = 0; k < 32; k++) preg[k] = pw[k * 64 + c];
    float pbc = pb[c];
#pragma unroll
    for (int gq = 0; gq < 4; gq++) {
        int nn = gbase + 4 * gq;
        float a = pbc;
#pragma unroll
        for (int k = 0; k < 32; k++) a = fmaf(xs[nn][k], preg[k], a);
        d_id[(n0 + nn) * 64 + c] = a;
    }
}

// K3: GAT1 fused aggregate + normalize + bias + LN(256) + ELU.
// TWO warps per node (each owns 128 channels / 2 heads), fp16 gathers,
// depth-2 software pipeline, per-lane single-head attention.
__global__ void k_agg1(const float* __restrict__ bias, const float* __restrict__ g,
                       const float* __restrict__ b2) {
    __shared__ float ssum[4][2], ssq[4][2];
    int t = threadIdx.x, lane = t & 31, w = t >> 5;
    int nl = w >> 1;                 // node within block (0..3)
    int n = blockIdx.x * 4 + nl;
    int hh = w & 1;                  // channel half (0: ch 0-127, 1: ch 128-255)
    int head = 2 * hh + (lane >> 4); // this lane's head
    const uint2* h64 = (const uint2*)d_h1h;  // 8B = 4 halves = 4 channels per lane

    float ad = d_ad1[n * 4 + head];
    // self-loop init
    float ex = expf(lrelu(d_as1[n * 4 + head] + ad));
    uint2 raw = h64[n * 64 + hh * 32 + lane];
    float2 fa = __half22float2(*(__half2*)&raw.x);
    float2 fb = __half22float2(*(__half2*)&raw.y);
    float a0 = ex * fa.x, a1 = ex * fa.y, a2 = ex * fb.x, a3 = ex * fb.y;
    float den = ex;

    int s = d_off[n], e = d_off[n + 1];
    float asA = 0.f, asB = 0.f;
    uint2 rA = make_uint2(0, 0), rB = rA;
    if (s < e) {
        int sc = d_csrc[s];
        asA = d_as1[sc * 4 + head];
        rA = h64[sc * 64 + hh * 32 + lane];
    }
    if (s + 1 < e) {
        int sc = d_csrc[s + 1];
        asB = d_as1[sc * 4 + head];
        rB = h64[sc * 64 + hh * 32 + lane];
    }
#pragma unroll 1
    for (int i = s; i < e; i++) {
        float asN = 0.f;
        uint2 rN = make_uint2(0, 0);
        if (i + 2 < e) {
            int sc = d_csrc[i + 2];
            asN = d_as1[sc * 4 + head];
            rN = h64[sc * 64 + hh * 32 + lane];
        }
        float ee = expf(lrelu(asA + ad));
        float2 va = __half22float2(*(__half2*)&rA.x);
        float2 vb = __half22float2(*(__half2*)&rA.y);
        a0 = fmaf(ee, va.x, a0);
        a1 = fmaf(ee, va.y, a1);
        a2 = fmaf(ee, vb.x, a2);
        a3 = fmaf(ee, vb.y, a3);
        den += ee;
        asA = asB; rA = rB;
        asB = asN; rB = rN;
    }
    float r = 1.f / (den + 1e-16f);
    float4 bb = ((const float4*)bias)[hh * 32 + lane];
    float v0 = a0 * r + bb.x, v1 = a1 * r + bb.y, v2 = a2 * r + bb.z, v3 = a3 * r + bb.w;
    float ps = wredsum(v0 + v1 + v2 + v3);
    float pq = wredsum(v0 * v0 + v1 * v1 + v2 * v2 + v3 * v3);
    if (lane == 0) { ssum[nl][hh] = ps; ssq[nl][hh] = pq; }
    __syncthreads();
    float S = ssum[nl][0] + ssum[nl][1];
    float Q = ssq[nl][0] + ssq[nl][1];
    float m = S * (1.f / 256.f);
    float var = Q * (1.f / 256.f) - m * m;
    float inv = rsqrtf(var + 1e-5f);
    float4 gg = ((const float4*)g)[hh * 32 + lane];
    float4 be = ((const float4*)b2)[hh * 32 + lane];
    float y0 = elu1((v0 - m) * inv * gg.x + be.x);
    float y1 = elu1((v1 - m) * inv * gg.y + be.y);
    float y2 = elu1((v2 - m) * inv * gg.z + be.z);
    float y3 = elu1((v3 - m) * inv * gg.w + be.w);
    __half2 o0 = __floats2half2_rn(y0, y1);
    __half2 o1 = __floats2half2_rn(y2, y3);
    uint2 packed;
    packed.x = *(unsigned int*)&o0;
    packed.y = *(unsigned int*)&o1;
    ((uint2*)d_hmidh)[n * 64 + hh * 32 + lane] = packed;
}

// transpose gat2 W: Wt[c][k] = W[k*64+c]
__global__ void k_wt(const float* __restrict__ W) {
    int idx = blockIdx.x * 256 + threadIdx.x;  // 16384
    int k = idx >> 6, c = idx & 63;
    d_wt[c * 256 + k] = W[idx];
}

// K5: gat2 linear h2 = hmid @ W(256,64) + attention scalars. 8 nodes/block.
// hmid read as fp16 (converted to fp32 smem), h2 written fp16.
__global__ void k_gat2_lin(const float* __restrict__ as_, const float* __restrict__ ad_) {
    __shared__ __align__(16) float sh[8][256];
    __shared__ __align__(16) float h2s[8][64];
    int t = threadIdx.x;
    int n0 = blockIdx.x * 8;
    // load 8 rows x 256 halves = 256 uint4 (8 halves each); one per thread
    {
        uint4 rw = ((const uint4*)d_hmidh)[n0 * 32 + t];
        int row = t >> 5, col = (t & 31) * 8;
        float2 f0 = __half22float2(*(__half2*)&rw.x);
        float2 f1 = __half22float2(*(__half2*)&rw.y);
        float2 f2 = __half22float2(*(__half2*)&rw.z);
        float2 f3 = __half22float2(*(__half2*)&rw.w);
        sh[row][col + 0] = f0.x; sh[row][col + 1] = f0.y;
        sh[row][col + 2] = f1.x; sh[row][col + 3] = f1.y;
        sh[row][col + 4] = f2.x; sh[row][col + 5] = f2.y;
        sh[row][col + 6] = f3.x; sh[row][col + 7] = f3.y;
    }
    __syncthreads();
    int c = t & 63, grp = t >> 6;
    const float4* wt4 = (const float4*)&d_wt[c * 256];
    const float4* s0p = (const float4*)sh[grp];
    const float4* s1p = (const float4*)sh[grp + 4];
    float acc0 = 0.f, acc1 = 0.f;
#pragma unroll 8
    for (int k4 = 0; k4 < 64; k4++) {
        float4 w = wt4[k4];
        float4 s0 = s0p[k4];
        float4 s1 = s1p[k4];
        acc0 = fmaf(s0.x, w.x, fmaf(s0.y, w.y, fmaf(s0.z, w.z, fmaf(s0.w, w.w, acc0))));
        acc1 = fmaf(s1.x, w.x, fmaf(s1.y, w.y, fmaf(s1.z, w.z, fmaf(s1.w, w.w, acc1))));
    }
    h2s[grp][c] = acc0;
    h2s[grp + 4][c] = acc1;
    __syncthreads();
    int w = t >> 5, lane = t & 31;
    float2 h = ((float2*)h2s[w])[lane];
    ((__half2*)d_h2h)[(n0 + w) * 32 + lane] = __floats2half2_rn(h.x, h.y);
    float ps = wredsum(h.x * as_[2 * lane] + h.y * as_[2 * lane + 1]);
    float pd = wredsum(h.x * ad_[2 * lane] + h.y * ad_[2 * lane + 1]);
    if (lane == 0) { d_as2[n0 + w] = ps; d_ad2[n0 + w] = pd; }
}

// K6: GAT2 fused aggregate + LN(64) + identity + ELU + pool. Warp per node,
// fp16 gathers, depth-3 software pipeline.
__global__ void k_agg2(const float* __restrict__ bias, const float* __restrict__ g,
                       const float* __restrict__ b2) {
    __shared__ float spool[64];
    int t = threadIdx.x, lane = t & 31, w = t >> 5;
    int n = blockIdx.x * 8 + w;
    if (t < 64) spool[t] = 0.f;
    __syncthreads();
    float adn = d_ad2[n];
    const __half2* h2f = (const __half2*)d_h2h;
    float exs = expf(lrelu(d_as2[n] + adn));
    float2 hv = __half22float2(h2f[n * 32 + lane]);
    float ax = exs * hv.x, ay = exs * hv.y;
    float den = exs;
    int s = d_off[n], e = d_off[n + 1];
    float asA = 0.f, asB = 0.f, asC = 0.f;
    __half2 vA = __floats2half2_rn(0.f, 0.f), vB = vA, vC = vA;
    if (s < e)     { int sc = d_csrc[s];     asA = d_as2[sc]; vA = h2f[sc * 32 + lane]; }
    if (s + 1 < e) { int sc = d_csrc[s + 1]; asB = d_as2[sc]; vB = h2f[sc * 32 + lane]; }
    if (s + 2 < e) { int sc = d_csrc[s + 2]; asC = d_as2[sc]; vC = h2f[sc * 32 + lane]; }
#pragma unroll 1
    for (int i = s; i < e; i++) {
        float asN = 0.f;
        __half2 vN = __floats2half2_rn(0.f, 0.f);
        if (i + 3 < e) { int sc = d_csrc[i + 3]; asN = d_as2[sc]; vN = h2f[sc * 32 + lane]; }
        float ex = expf(lrelu(asA + adn));
        float2 v = __half22float2(vA);
        ax = fmaf(ex, v.x, ax);
        ay = fmaf(ex, v.y, ay);
        den += ex;
        asA = asB; vA = vB;
        asB = asC; vB = vC;
        asC = asN; vC = vN;
    }
    float r = 1.f / (den + 1e-16f);
    float v0 = ax * r + bias[2 * lane];
    float v1 = ay * r + bias[2 * lane + 1];
    float sum = wredsum(v0 + v1);
    float sq = wredsum(v0 * v0 + v1 * v1);
    float m = sum * (1.f / 64.f);
    float var = sq * (1.f / 64.f) - m * m;
    float inv = rsqrtf(var + 1e-5f);
    float y0 = elu1((v0 - m) * inv * g[2 * lane] + b2[2 * lane] + d_id[n * 64 + 2 * lane]);
    float y1 = elu1((v1 - m) * inv * g[2 * lane + 1] + b2[2 * lane + 1] + d_id[n * 64 + 2 * lane + 1]);
    atomicAdd(&spool[2 * lane], y0);
    atomicAdd(&spool[2 * lane + 1], y1);
    __syncthreads();
    if (t < 64) atomicAdd(&d_pool[t], spool[t]);
}

// K8: traffic encoder + fusion + final LN. Single block.
__global__ void k_final(const float* __restrict__ traffic, const float* __restrict__ trw,
                        const float* __restrict__ trb, const float* __restrict__ trg,
                        const float* __restrict__ trbe, const float* __restrict__ fuw,
                        const float* __restrict__ fub, const float* __restrict__ fug,
                        const float* __restrict__ fube, float* __restrict__ out) {
    int t = threadIdx.x, lane = t & 31, w = t >> 5;
    __shared__ float comb[96];
    __shared__ float rs[8], rq[8];
    if (t < 64) comb[t] = d_pool[t] * (1.f / (float)NN);
    if (t >= 128 && t < 160) {
        int c = t - 128;
        float v = trb[c];
#pragma unroll
        for (int k = 0; k < 5; k++) v = fmaf(traffic[k], trw[k * 32 + c], v);
        v = fmaxf(v, 0.f);
        float m = wredsum(v) * (1.f / 32.f);
        float d = v - m;
        float var = wredsum(d * d) * (1.f / 32.f);
        comb[64 + c] = d * rsqrtf(var + 1e-5f) * trg[c] + trbe[c];
    }
    __syncthreads();
    float o = fub[t];
#pragma unroll 8
    for (int k = 0; k < 96; k++) o = fmaf(comb[k], fuw[k * 256 + t], o);
    o = fmaxf(o, 0.f);
    float s = wredsum(o);
    float q = wredsum(o * o);
    if (lane == 0) { rs[w] = s; rq[w] = q; }
    __syncthreads();
    float S = 0.f, Q = 0.f;
#pragma unroll
    for (int i = 0; i < 8; i++) { S += rs[i]; Q += rq[i]; }
    float m = S * (1.f / 256.f);
    float var = Q * (1.f / 256.f) - m * m;
    out[t] = (o - m) * rsqrtf(var + 1e-5f) * fug[t] + fube[t];
}

extern "C" void kernel_launch(void* const* d_in, const int* in_sizes, int n_in,
                              void* d_out, int out_size) {
    bool dictOrder = (n_in > 3 && in_sizes[3] == 2 * EE);
    int ix[30];
    if (dictOrder) {
        for (int i = 0; i < 30; i++) ix[i] = i;
    } else {
        ix[0] = 0; ix[1] = 1; ix[2] = 2; ix[3] = n_in - 1;
        for (int i = 4; i < 30; i++) ix[i] = i - 1;
    }
    const float* pos    = (const float*)d_in[ix[0]];
    const float* deg    = (const float*)d_in[ix[1]];
    const float* tr     = (const float*)d_in[ix[2]];
    const int*   eiw    = (const int*)d_in[ix[3]];
    const float* enc_w  = (const float*)d_in[ix[4]];
    const float* enc_b  = (const float*)d_in[ix[5]];
    const float* enc_g  = (const float*)d_in[ix[6]];
    const float* enc_be = (const float*)d_in[ix[7]];
    const float* g1w    = (const float*)d_in[ix[8]];
    const float* g1as   = (const float*)d_in[ix[9]];
    const float* g1ad   = (const float*)d_in[ix[10]];
    const float* g1b    = (const float*)d_in[ix[11]];
    const float* n1g    = (const float*)d_in[ix[12]];
    const float* n1b    = (const float*)d_in[ix[13]];
    const float* pw     = (const float*)d_in[ix[14]];
    const float* pb     = (const float*)d_in[ix[15]];
    const float* g2w    = (const float*)d_in[ix[16]];
    const float* g2as   = (const float*)d_in[ix[17]];
    const float* g2ad   = (const float*)d_in[ix[18]];
    const float* g2b    = (const float*)d_in[ix[19]];
    const float* n2g    = (const float*)d_in[ix[20]];
    const float* n2b    = (const float*)d_in[ix[21]];
    const float* trw    = (const float*)d_in[ix[22]];
    const float* trb    = (const float*)d_in[ix[23]];
    const float* trg    = (const float*)d_in[ix[24]];
    const float* trbe   = (const float*)d_in[ix[25]];
    const float* fuw    = (const float*)d_in[ix[26]];
    const float* fub    = (const float*)d_in[ix[27]];
    const float* fug    = (const float*)d_in[ix[28]];
    const float* fube   = (const float*)d_in[ix[29]];

    k_detect<<<1, 32>>>(eiw);
    k_zero<<<(NN + 255) / 256, 256>>>();
    k_prep<<<1, 128>>>(g1w, g1as, g1ad);
    k_hist<<<EE / 256, 256>>>(eiw);
    k_scan1<<<SCAN_BLOCKS, 1024>>>();
    k_scan2<<<1, 64>>>();
    k_scan3<<<SCAN_BLOCKS, 1024>>>();
    k_scatter<<<EE / 256, 256>>>(eiw);
    k_encode<<<NN / 8, 256>>>(pos, deg, enc_w, enc_b, enc_g, enc_be);
    k_gat1_lin<<<NN / 16, 256>>>(g1w, pw, pb);
    k_agg1<<<NN / 4, 256>>>(g1b, n1g, n1b);
    k_wt<<<64, 256>>>(g2w);
    k_gat2_lin<<<NN / 8, 256>>>(g2as, g2ad);
    k_agg2<<<NN / 8, 256>>>(g2b, n2g, n2b);
    k_final<<<1, 256>>>(tr, trw, trb, trg, trbe, fuw, fub, fug, fube, (float*)d_out);
}